// round 16
// baseline (speedup 1.0000x reference)
#include <cuda_runtime.h>
#include <cuda_fp16.h>
#include <cstdint>
#include <math.h>

// ---------------------------------------------------------------------------
// Problem dims
// ---------------------------------------------------------------------------
#define T_STEPS 128
#define B_SZ    512
#define IN_SZ   784
#define H_SZ    2048
#define OUT_SZ  10
#define MB      (T_STEPS * B_SZ)          // 65536 GEMM rows
#define BH      (B_SZ * H_SZ)             // 1048576 neurons

#define KTP     800                       // K padded (zeros 784..799)
#define KAP     1600                      // packed row stride in halfs: [hi|lo]

// GEMM tiling: 128x128 CTA, 4 warps (2x2) of 64x64, BK=32, 2-stage pipeline
#define BN_T    128
#define BK_T    32                        // K per stage = two m16n8k16 sub-chunks
#define NSTG    25                        // 800 / 32
#define RB      80                        // smem row bytes (64B data + 16B pad)
#define REGION  (128 * RB)                // 10240 B: one of {Ahi,Alo,Bhi,Blo}
#define STAGEB  (4 * REGION)              // 40960 B per stage
#define SMEMB   (2 * STAGEB)              // 81920 B (2 stages, 2 CTAs/SM)
#define CPAD    132                       // C-tile smem row stride (floats)

// Scratch (device globals — no runtime allocation allowed)
__device__ __half g_A[(size_t)MB * KAP];       // 210 MB packed [hi|lo] X, rows b*128+t
__device__ __half g_B[(size_t)H_SZ * KAP];     // 6.6 MB packed [hi|lo] W1
__device__ float  g_S[(size_t)B_SZ * H_SZ];    // weighted spike sums
__device__ float  g_coef[T_STEPS];

// ---------------------------------------------------------------------------
// PTX helpers (arch-agnostic only: cp.async + mma.sync)
// ---------------------------------------------------------------------------
__device__ __forceinline__ uint32_t smem_u32(const void* p) {
    uint32_t a;
    asm("{ .reg .u64 t; cvta.to.shared.u64 t, %1; cvt.u32.u64 %0, t; }"
        : "=r"(a) : "l"(p));
    return a;
}
#define CP16(dst, src) \
    asm volatile("cp.async.cg.shared.global [%0], [%1], 16;" :: "r"(dst), "l"(src) : "memory")
#define CP_COMMIT() asm volatile("cp.async.commit_group;" ::: "memory")
#define CP_WAIT0()  asm volatile("cp.async.wait_group 0;" ::: "memory")

#define LDS32(reg, addr) \
    asm volatile("ld.shared.b32 %0, [%1];" : "=r"(reg) : "r"(addr))

// D += A*B  (m16n8k16, fp16 inputs packed f16x2 in b32 regs, fp32 accumulate)
#define MMA_F16(c, a, b)                                                       \
    asm volatile(                                                              \
        "mma.sync.aligned.m16n8k16.row.col.f32.f16.f16.f32 "                   \
        "{%0,%1,%2,%3}, {%4,%5,%6,%7}, {%8,%9}, {%0,%1,%2,%3};"                \
        : "+f"((c)[0]), "+f"((c)[1]), "+f"((c)[2]), "+f"((c)[3])               \
        : "r"((a)[0]), "r"((a)[1]), "r"((a)[2]), "r"((a)[3]),                  \
          "r"((b)[0]), "r"((b)[1]))

// ---------------------------------------------------------------------------
// Kernel 0: readout coefficients  c_t = 0.9^(127-t) - 0.8^(127-t)
// ---------------------------------------------------------------------------
__global__ void coef_kernel() {
    int t = threadIdx.x;
    if (t < T_STEPS) {
        float m = (float)(T_STEPS - 1 - t);
        g_coef[t] = powf(0.9f, m) - powf(0.8f, m);
    }
}

// ---------------------------------------------------------------------------
// Pack kernels: split fp32 -> (hi, lo) fp16 pairs, K padded 784->800 (zeros).
// A is row-PERMUTED: packed row m = b*128 + t reads x[t, b, :].
// ---------------------------------------------------------------------------
__global__ __launch_bounds__(256)
void packA_kernel(const float* __restrict__ x) {
    size_t m = blockIdx.x;                 // b*128 + t
    int b = (int)(m >> 7);
    int t = (int)(m & 127);
    const float* src = x + ((size_t)t * B_SZ + b) * IN_SZ;
    __half* dst = g_A + m * KAP;
    for (int k = threadIdx.x; k < KTP; k += 256) {
        float v = (k < IN_SZ) ? src[k] : 0.0f;
        __half h = __float2half_rn(v);
        dst[k] = h;
        dst[KTP + k] = __float2half_rn(v - __half2float(h));
    }
}
__global__ __launch_bounds__(256)
void packB_kernel(const float* __restrict__ w) {
    size_t n = blockIdx.x;
    const float* src = w + n * IN_SZ;
    __half* dst = g_B + n * KAP;
    for (int k = threadIdx.x; k < KTP; k += 256) {
        float v = (k < IN_SZ) ? src[k] : 0.0f;
        __half h = __float2half_rn(v);
        dst[k] = h;
        dst[KTP + k] = __float2half_rn(v - __half2float(h));
    }
}

// ---------------------------------------------------------------------------
// Fused GEMM + LIF scan. fp16x3 mma.sync m16n8k16, 128x128 CTA, 4 warps of
// 64x64, BK=32 / 2-stage cp.async (half the barriers of the BK=16 version),
// 2 CTAs/SM. Tile = (batch element b: t=0..127) x (128 hidden units);
// epilogue dumps C to smem and scans LIF in-CTA, writing S[b,h].
// Per-acc order (hh->hl->lh per k16 chunk, chunks ascending) + zero padding
// -> bit-identical to the 2408us kernel.
// ---------------------------------------------------------------------------
__global__ __launch_bounds__(128, 2)
void mma_kernel() {
    extern __shared__ __align__(16) char smem[];
    const uint32_t sbase = smem_u32(smem);

    const int tid  = threadIdx.x;
    const int wid  = tid >> 5;
    const int lane = tid & 31;
    const int lq   = lane >> 2;           // 0..7
    const int lr   = lane & 3;            // 0..3
    const int warp_m = wid & 1;           // 2 strips of 64 rows (t)
    const int warp_n = wid >> 1;          // 2 strips of 64 cols (h)

    const int n0 = blockIdx.x * BN_T;     // x fastest -> A-tile L2 reuse
    const int m0 = blockIdx.y * 128;      // = b * 128
    const int bidx = blockIdx.y;          // batch element

    // ---- producer mapping: thread t owns row t of all 4 regions ----
    // per stage: 16 x CP16 per thread (4 per region: 64B data per row)
    const int prow = tid;                 // 0..127
    const __half* ga = g_A + (size_t)(m0 + prow) * KAP;
    const __half* gb = g_B + (size_t)(n0 + prow) * KAP;
    const uint32_t prowoff = (uint32_t)prow * RB;

    float acc[4][8][4];
#pragma unroll
    for (int mi = 0; mi < 4; mi++)
#pragma unroll
        for (int ni = 0; ni < 8; ni++)
#pragma unroll
            for (int q = 0; q < 4; q++) acc[mi][ni][q] = 0.0f;

    // fragment base byte-offsets within a region
    const uint32_t a_off0 = (uint32_t)(warp_m * 64 + lq) * RB + (uint32_t)lr * 4u;
    const uint32_t b_off0 = (uint32_t)(warp_n * 64 + lq) * RB + (uint32_t)lr * 4u;

#define LOAD_STAGE(buf, kc) do {                                               \
    uint32_t st = sbase + (uint32_t)(buf) * STAGEB;                            \
    const __half* ga_h = ga + (kc);                                            \
    const __half* gb_h = gb + (kc);                                            \
    _Pragma("unroll")                                                          \
    for (int j = 0; j < 4; j++) {                                              \
        uint32_t d = prowoff + (uint32_t)j * 16u;                              \
        CP16(st + 0 * REGION + d, ga_h + j * 8);                               \
        CP16(st + 1 * REGION + d, ga_h + KTP + j * 8);                         \
        CP16(st + 2 * REGION + d, gb_h + j * 8);                               \
        CP16(st + 3 * REGION + d, gb_h + KTP + j * 8);                         \
    } } while (0)

    // prologue: stage 0 committed
    LOAD_STAGE(0, 0);  CP_COMMIT();

    for (int k = 0; k < NSTG; k++) {
        CP_WAIT0();                 // stage k resident
        __syncthreads();            // all warps done with stage k-1 buffer

        // prefetch stage k+1 into buffer (k+1)&1 (freed above); it completes
        // while the ~2x-longer BK=32 compute below runs.
        if (k + 1 < NSTG) LOAD_STAGE((k + 1) & 1, (k + 1) * BK_T);
        CP_COMMIT();                // always commit (empty ok) to keep count

        const uint32_t st = sbase + (uint32_t)(k & 1) * STAGEB;
        const uint32_t sa_h = st + 0 * REGION + a_off0;
        const uint32_t sa_l = st + 1 * REGION + a_off0;
        const uint32_t sb_h = st + 2 * REGION + b_off0;
        const uint32_t sb_l = st + 3 * REGION + b_off0;

        // two k16 sub-chunks per stage
#pragma unroll
        for (int c = 0; c < 2; c++) {
            const uint32_t co = (uint32_t)c * 32u;

            // ---- preload fragments for this sub-chunk (64 LDS32) ----
            uint32_t ah[4][4], al[4][4], bh[8][2], bl[8][2];
#pragma unroll
            for (int mi = 0; mi < 4; mi++) {
                uint32_t base = (uint32_t)mi * (16u * RB) + co;
                LDS32(ah[mi][0], sa_h + base);
                LDS32(ah[mi][1], sa_h + base + 8u * RB);
                LDS32(ah[mi][2], sa_h + base + 16u);
                LDS32(ah[mi][3], sa_h + base + 8u * RB + 16u);
                LDS32(al[mi][0], sa_l + base);
                LDS32(al[mi][1], sa_l + base + 8u * RB);
                LDS32(al[mi][2], sa_l + base + 16u);
                LDS32(al[mi][3], sa_l + base + 8u * RB + 16u);
            }
#pragma unroll
            for (int ni = 0; ni < 8; ni++) {
                uint32_t base = (uint32_t)ni * (8u * RB) + co;
                LDS32(bh[ni][0], sb_h + base);
                LDS32(bh[ni][1], sb_h + base + 16u);
                LDS32(bl[ni][0], sb_l + base);
                LDS32(bl[ni][1], sb_l + base + 16u);
            }

            // ---- 96 MMAs: term-outer; per-acc order hh -> hl -> lh ----
#pragma unroll
            for (int mi = 0; mi < 4; mi++)
#pragma unroll
                for (int ni = 0; ni < 8; ni++)
                    MMA_F16(acc[mi][ni], ah[mi], bh[ni]);   // hi*hi
#pragma unroll
            for (int mi = 0; mi < 4; mi++)
#pragma unroll
                for (int ni = 0; ni < 8; ni++)
                    MMA_F16(acc[mi][ni], ah[mi], bl[ni]);   // hi*lo
#pragma unroll
            for (int mi = 0; mi < 4; mi++)
#pragma unroll
                for (int ni = 0; ni < 8; ni++)
                    MMA_F16(acc[mi][ni], al[mi], bh[ni]);   // lo*hi
        }
    }

    // ======================= fused epilogue: LIF scan =======================
    CP_WAIT0();
    __syncthreads();

    float* Csm = (float*)smem;            // [128 t][CPAD] = 67584 B <= 81920
#pragma unroll
    for (int mi = 0; mi < 4; mi++) {
        const int r0 = warp_m * 64 + mi * 16 + lq;       // t row
        const int c0 = warp_n * 64 + lr * 2;             // h col base
        float* w0 = Csm + (size_t)r0 * CPAD + c0;
        float* w1 = Csm + (size_t)(r0 + 8) * CPAD + c0;
#pragma unroll
        for (int ni = 0; ni < 8; ni++) {
            *(float2*)(w0 + ni * 8) = make_float2(acc[mi][ni][0], acc[mi][ni][1]);
            *(float2*)(w1 + ni * 8) = make_float2(acc[mi][ni][2], acc[mi][ni][3]);
        }
    }
    __syncthreads();

    // thread j scans hidden unit (n0 + j) of batch element bidx over t=0..127
    {
        float v = 0.0f, ii = 0.0f, s = 0.0f;
        const float* col = Csm + tid;
        for (int t = 0; t < T_STEPS; t++) {
            float c = col[(size_t)t * CPAD];
            float coef = g_coef[t];
            float vd = v + 0.1f * ((0.0f - v) + ii);
            float id = 0.8f * ii;
            if ((vd - 0.25f) > 0.0f) { v = 0.0f; s += coef; } else { v = vd; }
            ii = id + c;
        }
        g_S[(size_t)bidx * H_SZ + n0 + tid] = s;
    }
#undef LOAD_STAGE
}

// ---------------------------------------------------------------------------
// Readout: vo = S @ Wout^T
// ---------------------------------------------------------------------------
__global__ __launch_bounds__(256)
void readout_kernel(const float* __restrict__ Wout, float* __restrict__ out) {
    const int b = blockIdx.x;
    const int tid = threadIdx.x;
    float acc[OUT_SZ];
#pragma unroll
    for (int o = 0; o < OUT_SZ; o++) acc[o] = 0.0f;

    const float* srow = g_S + (size_t)b * H_SZ;
    for (int h = tid; h < H_SZ; h += 256) {
        float sv = srow[h];
#pragma unroll
        for (int o = 0; o < OUT_SZ; o++)
            acc[o] = fmaf(sv, __ldg(&Wout[o * H_SZ + h]), acc[o]);
    }
    __shared__ float red[OUT_SZ][8];
    const int lane = tid & 31, warp = tid >> 5;
#pragma unroll
    for (int o = 0; o < OUT_SZ; o++) {
        float v = acc[o];
#pragma unroll
        for (int off = 16; off; off >>= 1) v += __shfl_down_sync(0xffffffffu, v, off);
        if (lane == 0) red[o][warp] = v;
    }
    __syncthreads();
    if (tid < OUT_SZ) {
        float v = 0.0f;
#pragma unroll
        for (int w = 0; w < 8; w++) v += red[tid][w];
        out[b * OUT_SZ + tid] = v;
    }
}

// ---------------------------------------------------------------------------
extern "C" void kernel_launch(void* const* d_in, const int* in_sizes, int n_in,
                              void* d_out, int out_size) {
    const float* x    = (const float*)d_in[0];   // [128,512,784]
    const float* W1   = (const float*)d_in[1];   // [2048,784]
    const float* Wout = (const float*)d_in[2];   // [10,2048]
    float* out = (float*)d_out;                  // [512,10]

    coef_kernel<<<1, 128>>>();
    packA_kernel<<<MB, 256>>>(x);
    packB_kernel<<<H_SZ, 256>>>(W1);

    cudaFuncSetAttribute(mma_kernel, cudaFuncAttributeMaxDynamicSharedMemorySize, SMEMB);
    dim3 grid(H_SZ / BN_T, B_SZ);        // (16, 512), x fastest
    mma_kernel<<<grid, 128, SMEMB>>>();

    readout_kernel<<<B_SZ, 256>>>(Wout, out);
}

// round 17
// speedup vs baseline: 1.0984x; 1.0984x over previous
#include <cuda_runtime.h>
#include <cuda_fp16.h>
#include <cstdint>
#include <math.h>

// ---------------------------------------------------------------------------
// Problem dims
// ---------------------------------------------------------------------------
#define T_STEPS 128
#define B_SZ    512
#define IN_SZ   784
#define H_SZ    2048
#define OUT_SZ  10
#define MB      (T_STEPS * B_SZ)          // 65536 GEMM rows
#define BH      (B_SZ * H_SZ)             // 1048576 neurons

#define KT      784                       // K elements
#define KAP     1568                      // packed row stride in halfs: [hi|lo]
#define KQ      196                       // 784 / 4 (float4 chunks per row)

// GEMM tiling (R14-best): 128x128 CTA, 4 warps (2x2) of 64x64, BK=16, 4 stages
#define BN_T    128
#define BK_T    16
#define NSTG    49                        // 784 / 16
#define RB      48                        // smem row bytes (32B data + 16B pad)
#define REGION  (128 * RB)                // 6144 B
#define STAGEB  (4 * REGION)              // 24576 B per stage
#define SMEMB   (4 * STAGEB)              // 98304 B (4 stages, 2 CTAs/SM)
#define CPAD    132                       // C-tile smem row stride (floats)

// Scratch (device globals — no runtime allocation allowed)
__device__ __half g_A[(size_t)MB * KAP];       // 205 MB packed [hi|lo] X, rows b*128+t
__device__ __half g_B[(size_t)H_SZ * KAP];     // 6.4 MB packed [hi|lo] W1
__device__ float  g_S[(size_t)B_SZ * H_SZ];    // weighted spike sums
__device__ float  g_coef[T_STEPS];

// ---------------------------------------------------------------------------
// PTX helpers (arch-agnostic only: cp.async + mma.sync)
// ---------------------------------------------------------------------------
__device__ __forceinline__ uint32_t smem_u32(const void* p) {
    uint32_t a;
    asm("{ .reg .u64 t; cvta.to.shared.u64 t, %1; cvt.u32.u64 %0, t; }"
        : "=r"(a) : "l"(p));
    return a;
}
#define CP16(dst, src) \
    asm volatile("cp.async.cg.shared.global [%0], [%1], 16;" :: "r"(dst), "l"(src) : "memory")
#define CP_COMMIT() asm volatile("cp.async.commit_group;" ::: "memory")
#define CP_WAIT2()  asm volatile("cp.async.wait_group 2;" ::: "memory")
#define CP_WAIT0()  asm volatile("cp.async.wait_group 0;" ::: "memory")

#define LDS32(reg, addr) \
    asm volatile("ld.shared.b32 %0, [%1];" : "=r"(reg) : "r"(addr))

// D += A*B  (m16n8k16, fp16 inputs packed f16x2 in b32 regs, fp32 accumulate)
#define MMA_F16(c, a, b)                                                       \
    asm volatile(                                                              \
        "mma.sync.aligned.m16n8k16.row.col.f32.f16.f16.f32 "                   \
        "{%0,%1,%2,%3}, {%4,%5,%6,%7}, {%8,%9}, {%0,%1,%2,%3};"                \
        : "+f"((c)[0]), "+f"((c)[1]), "+f"((c)[2]), "+f"((c)[3])               \
        : "r"((a)[0]), "r"((a)[1]), "r"((a)[2]), "r"((a)[3]),                  \
          "r"((b)[0]), "r"((b)[1]))

// ---------------------------------------------------------------------------
// Kernel 0: readout coefficients  c_t = 0.9^(127-t) - 0.8^(127-t)
// ---------------------------------------------------------------------------
__global__ void coef_kernel() {
    int t = threadIdx.x;
    if (t < T_STEPS) {
        float m = (float)(T_STEPS - 1 - t);
        g_coef[t] = powf(0.9f, m) - powf(0.8f, m);
    }
}

// ---------------------------------------------------------------------------
// Pack kernels (vectorized): fp32 -> (hi, lo) fp16 pairs via float4 / half2.
// A is row-PERMUTED: packed row m = b*128 + t reads x[t, b, :].
// 2 rows per 256-thread block.
// ---------------------------------------------------------------------------
__global__ __launch_bounds__(256)
void packA_kernel(const float* __restrict__ x) {
    const size_t m = (size_t)blockIdx.x * 2 + (threadIdx.x >> 7);
    const int tl = threadIdx.x & 127;
    const int b = (int)(m >> 7);
    const int t = (int)(m & 127);
    const float4* src = (const float4*)(x + ((size_t)t * B_SZ + b) * IN_SZ);
    __half2* dhi = (__half2*)(g_A + m * KAP);
    __half2* dlo = (__half2*)(g_A + m * KAP + KT);
#pragma unroll 2
    for (int q = tl; q < KQ; q += 128) {
        float4 v = __ldg(&src[q]);
        __half hx = __float2half_rn(v.x), hy = __float2half_rn(v.y);
        __half hz = __float2half_rn(v.z), hw = __float2half_rn(v.w);
        dhi[q * 2 + 0] = __halves2half2(hx, hy);
        dhi[q * 2 + 1] = __halves2half2(hz, hw);
        dlo[q * 2 + 0] = __halves2half2(__float2half_rn(v.x - __half2float(hx)),
                                        __float2half_rn(v.y - __half2float(hy)));
        dlo[q * 2 + 1] = __halves2half2(__float2half_rn(v.z - __half2float(hz)),
                                        __float2half_rn(v.w - __half2float(hw)));
    }
}
__global__ __launch_bounds__(256)
void packB_kernel(const float* __restrict__ w) {
    const size_t n = (size_t)blockIdx.x * 2 + (threadIdx.x >> 7);
    const int tl = threadIdx.x & 127;
    const float4* src = (const float4*)(w + n * IN_SZ);
    __half2* dhi = (__half2*)(g_B + n * KAP);
    __half2* dlo = (__half2*)(g_B + n * KAP + KT);
#pragma unroll 2
    for (int q = tl; q < KQ; q += 128) {
        float4 v = __ldg(&src[q]);
        __half hx = __float2half_rn(v.x), hy = __float2half_rn(v.y);
        __half hz = __float2half_rn(v.z), hw = __float2half_rn(v.w);
        dhi[q * 2 + 0] = __halves2half2(hx, hy);
        dhi[q * 2 + 1] = __halves2half2(hz, hw);
        dlo[q * 2 + 0] = __halves2half2(__float2half_rn(v.x - __half2float(hx)),
                                        __float2half_rn(v.y - __half2float(hy)));
        dlo[q * 2 + 1] = __halves2half2(__float2half_rn(v.z - __half2float(hz)),
                                        __float2half_rn(v.w - __half2float(hw)));
    }
}

// ---------------------------------------------------------------------------
// Fused GEMM + LIF scan (R14 verbatim). fp16x3 mma.sync m16n8k16, 128x128 CTA,
// 4 warps of 64x64, BK=16, 4-stage cp.async, 2 CTAs/SM. Tile = (batch element
// b: t=0..127) x (128 hidden units); epilogue dumps C to smem and scans LIF
// in-CTA, writing S[b,h]. Bit-identical to the 2408us kernel.
// ---------------------------------------------------------------------------
__global__ __launch_bounds__(128, 2)
void mma_kernel() {
    extern __shared__ __align__(16) char smem[];
    const uint32_t sbase = smem_u32(smem);

    const int tid  = threadIdx.x;
    const int wid  = tid >> 5;
    const int lane = tid & 31;
    const int lq   = lane >> 2;           // 0..7
    const int lr   = lane & 3;            // 0..3
    const int warp_m = wid & 1;           // 2 strips of 64 rows (t)
    const int warp_n = wid >> 1;          // 2 strips of 64 cols (h)

    const int n0 = blockIdx.x * BN_T;     // x fastest -> A-tile L2 reuse
    const int m0 = blockIdx.y * 128;      // = b * 128
    const int bidx = blockIdx.y;          // batch element

    const int prow = tid;                 // 0..127
    const __half* ga = g_A + (size_t)(m0 + prow) * KAP;
    const __half* gb = g_B + (size_t)(n0 + prow) * KAP;
    const uint32_t prowoff = (uint32_t)prow * RB;

    float acc[4][8][4];
#pragma unroll
    for (int mi = 0; mi < 4; mi++)
#pragma unroll
        for (int ni = 0; ni < 8; ni++)
#pragma unroll
            for (int q = 0; q < 4; q++) acc[mi][ni][q] = 0.0f;

    const uint32_t a_off0 = (uint32_t)(warp_m * 64 + lq) * RB + (uint32_t)lr * 4u;
    const uint32_t b_off0 = (uint32_t)(warp_n * 64 + lq) * RB + (uint32_t)lr * 4u;

#define LOAD_STAGE(buf, kc) do {                                               \
    uint32_t st = sbase + (uint32_t)(buf) * STAGEB;                            \
    const __half* ga_h = ga + (kc);                                            \
    const __half* gb_h = gb + (kc);                                            \
    CP16(st + 0 * REGION + prowoff,       ga_h);                               \
    CP16(st + 0 * REGION + prowoff + 16u, ga_h + 8);                           \
    CP16(st + 1 * REGION + prowoff,       ga_h + KT);                          \
    CP16(st + 1 * REGION + prowoff + 16u, ga_h + KT + 8);                      \
    CP16(st + 2 * REGION + prowoff,       gb_h);                               \
    CP16(st + 2 * REGION + prowoff + 16u, gb_h + 8);                           \
    CP16(st + 3 * REGION + prowoff,       gb_h + KT);                          \
    CP16(st + 3 * REGION + prowoff + 16u, gb_h + KT + 8);                      \
    } while (0)

    // prologue: stages 0..2 committed (3 groups outstanding)
    LOAD_STAGE(0, 0);  CP_COMMIT();
    LOAD_STAGE(1, 16); CP_COMMIT();
    LOAD_STAGE(2, 32); CP_COMMIT();

    for (int k = 0; k < NSTG; k++) {
        CP_WAIT2();                 // stage k resident (<=2 groups outstanding)
        __syncthreads();            // everyone done with stage k-1 buffer

        // prefetch stage k+3 into buffer (k+3)&3 == (k-1)&3 (freed above)
        if (k + 3 < NSTG) LOAD_STAGE((k + 3) & 3, (k + 3) * BK_T);
        CP_COMMIT();                // always commit (empty ok) to keep count

        const uint32_t st = sbase + (uint32_t)(k & 3) * STAGEB;
        const uint32_t sa_h = st + 0 * REGION + a_off0;
        const uint32_t sa_l = st + 1 * REGION + a_off0;
        const uint32_t sb_h = st + 2 * REGION + b_off0;
        const uint32_t sb_l = st + 3 * REGION + b_off0;

        // ---- preload all fragments (64 LDS32) ----
        uint32_t ah[4][4], al[4][4], bh[8][2], bl[8][2];
#pragma unroll
        for (int mi = 0; mi < 4; mi++) {
            uint32_t base = (uint32_t)mi * (16u * RB);
            LDS32(ah[mi][0], sa_h + base);
            LDS32(ah[mi][1], sa_h + base + 8u * RB);
            LDS32(ah[mi][2], sa_h + base + 16u);
            LDS32(ah[mi][3], sa_h + base + 8u * RB + 16u);
            LDS32(al[mi][0], sa_l + base);
            LDS32(al[mi][1], sa_l + base + 8u * RB);
            LDS32(al[mi][2], sa_l + base + 16u);
            LDS32(al[mi][3], sa_l + base + 8u * RB + 16u);
        }
#pragma unroll
        for (int ni = 0; ni < 8; ni++) {
            uint32_t base = (uint32_t)ni * (8u * RB);
            LDS32(bh[ni][0], sb_h + base);
            LDS32(bh[ni][1], sb_h + base + 16u);
            LDS32(bl[ni][0], sb_l + base);
            LDS32(bl[ni][1], sb_l + base + 16u);
        }

        // ---- 96 MMAs: term-outer; per-acc order hh -> hl -> lh ----
#pragma unroll
        for (int mi = 0; mi < 4; mi++)
#pragma unroll
            for (int ni = 0; ni < 8; ni++)
                MMA_F16(acc[mi][ni], ah[mi], bh[ni]);   // hi*hi
#pragma unroll
        for (int mi = 0; mi < 4; mi++)
#pragma unroll
            for (int ni = 0; ni < 8; ni++)
                MMA_F16(acc[mi][ni], ah[mi], bl[ni]);   // hi*lo
#pragma unroll
        for (int mi = 0; mi < 4; mi++)
#pragma unroll
            for (int ni = 0; ni < 8; ni++)
                MMA_F16(acc[mi][ni], al[mi], bh[ni]);   // lo*hi
    }

    // ======================= fused epilogue: LIF scan =======================
    CP_WAIT0();
    __syncthreads();

    float* Csm = (float*)smem;            // [128 t][CPAD] = 67584 B <= 98304
#pragma unroll
    for (int mi = 0; mi < 4; mi++) {
        const int r0 = warp_m * 64 + mi * 16 + lq;       // t row
        const int c0 = warp_n * 64 + lr * 2;             // h col base
        float* w0 = Csm + (size_t)r0 * CPAD + c0;
        float* w1 = Csm + (size_t)(r0 + 8) * CPAD + c0;
#pragma unroll
        for (int ni = 0; ni < 8; ni++) {
            *(float2*)(w0 + ni * 8) = make_float2(acc[mi][ni][0], acc[mi][ni][1]);
            *(float2*)(w1 + ni * 8) = make_float2(acc[mi][ni][2], acc[mi][ni][3]);
        }
    }
    __syncthreads();

    // thread j scans hidden unit (n0 + j) of batch element bidx over t=0..127
    {
        float v = 0.0f, ii = 0.0f, s = 0.0f;
        const float* col = Csm + tid;
        for (int t = 0; t < T_STEPS; t++) {
            float c = col[(size_t)t * CPAD];
            float coef = g_coef[t];
            float vd = v + 0.1f * ((0.0f - v) + ii);
            float id = 0.8f * ii;
            if ((vd - 0.25f) > 0.0f) { v = 0.0f; s += coef; } else { v = vd; }
            ii = id + c;
        }
        g_S[(size_t)bidx * H_SZ + n0 + tid] = s;
    }
#undef LOAD_STAGE
}

// ---------------------------------------------------------------------------
// Readout: vo = S @ Wout^T
// ---------------------------------------------------------------------------
__global__ __launch_bounds__(256)
void readout_kernel(const float* __restrict__ Wout, float* __restrict__ out) {
    const int b = blockIdx.x;
    const int tid = threadIdx.x;
    float acc[OUT_SZ];
#pragma unroll
    for (int o = 0; o < OUT_SZ; o++) acc[o] = 0.0f;

    const float* srow = g_S + (size_t)b * H_SZ;
    for (int h = tid; h < H_SZ; h += 256) {
        float sv = srow[h];
#pragma unroll
        for (int o = 0; o < OUT_SZ; o++)
            acc[o] = fmaf(sv, __ldg(&Wout[o * H_SZ + h]), acc[o]);
    }
    __shared__ float red[OUT_SZ][8];
    const int lane = tid & 31, warp = tid >> 5;
#pragma unroll
    for (int o = 0; o < OUT_SZ; o++) {
        float v = acc[o];
#pragma unroll
        for (int off = 16; off; off >>= 1) v += __shfl_down_sync(0xffffffffu, v, off);
        if (lane == 0) red[o][warp] = v;
    }
    __syncthreads();
    if (tid < OUT_SZ) {
        float v = 0.0f;
#pragma unroll
        for (int w = 0; w < 8; w++) v += red[tid][w];
        out[b * OUT_SZ + tid] = v;
    }
}

// ---------------------------------------------------------------------------
extern "C" void kernel_launch(void* const* d_in, const int* in_sizes, int n_in,
                              void* d_out, int out_size) {
    const float* x    = (const float*)d_in[0];   // [128,512,784]
    const float* W1   = (const float*)d_in[1];   // [2048,784]
    const float* Wout = (const float*)d_in[2];   // [10,2048]
    float* out = (float*)d_out;                  // [512,10]

    coef_kernel<<<1, 128>>>();
    packA_kernel<<<MB / 2, 256>>>(x);
    packB_kernel<<<H_SZ / 2, 256>>>(W1);

    cudaFuncSetAttribute(mma_kernel, cudaFuncAttributeMaxDynamicSharedMemorySize, SMEMB);
    dim3 grid(H_SZ / BN_T, B_SZ);        // (16, 512), x fastest
    mma_kernel<<<grid, 128, SMEMB>>>();

    readout_kernel<<<B_SZ, 256>>>(Wout, out);
}